// round 1
// baseline (speedup 1.0000x reference)
#include <cuda_runtime.h>
#include <cstdint>
#include <cstddef>

// Problem constants (fixed shapes)
#define NMAX 100000
#define DD   128
#define D2   256
#define GCNT 512

// ---------------- device scratch ----------------
__device__ float g_x  [NMAX * DD];   // current node features
__device__ float g_hin[NMAX * DD];   // (1+eps)*x + aggregation
__device__ float g_y  [NMAX * D2];   // GEMM1 output (pre-BN)
__device__ float g_h2 [NMAX * DD];   // GEMM2 output (pre-BN)
__device__ float g_ssum[D2];
__device__ float g_ssq [D2];
__device__ float g_scale[D2];
__device__ float g_shift[D2];
__device__ float g_ps [GCNT * DD];
__device__ float g_pmx[GCNT * DD];
__device__ float g_cnt[GCNT];
__device__ float g_z1 [GCNT * DD];
__device__ int   g_i64flag;

// ---------------- dtype detection (int32 vs int64 indices) ----------------
__global__ void detect_k(const unsigned int* __restrict__ e) {
    unsigned acc = 0;
    for (int i = 1; i < 128; i += 2) acc |= e[i];
    g_i64flag = (acc == 0u) ? 1 : 0;
}

// ---------------- prep kernels ----------------
__global__ void prep0_k(const float4* __restrict__ x, const float* __restrict__ epsp, int n32) {
    int i = blockIdx.x * blockDim.x + threadIdx.x;
    if (i < n32) {
        float e = 1.0f + epsp[0];
        float4 v = x[i];
        ((float4*)g_x)[i] = v;
        ((float4*)g_hin)[i] = make_float4(v.x * e, v.y * e, v.z * e, v.w * e);
    }
    if (i < D2) { g_ssum[i] = 0.f; g_ssq[i] = 0.f; }
}

// x_cur = relu(bn(h2)); hin = (1+eps_l)*x_cur
__global__ void prep_k(const float* __restrict__ epsp, int l, int n32) {
    int i = blockIdx.x * blockDim.x + threadIdx.x;
    if (i < n32) {
        float e = 1.0f + epsp[l];
        int c = (i & 31) * 4;
        float4 v = ((const float4*)g_h2)[i];
        float4 r;
        r.x = fmaxf(fmaf(v.x, g_scale[c + 0], g_shift[c + 0]), 0.f);
        r.y = fmaxf(fmaf(v.y, g_scale[c + 1], g_shift[c + 1]), 0.f);
        r.z = fmaxf(fmaf(v.z, g_scale[c + 2], g_shift[c + 2]), 0.f);
        r.w = fmaxf(fmaf(v.w, g_scale[c + 3], g_shift[c + 3]), 0.f);
        ((float4*)g_x)[i] = r;
        ((float4*)g_hin)[i] = make_float4(r.x * e, r.y * e, r.z * e, r.w * e);
    }
}

// ---------------- edge scatter-add: hin[dst] += x[src] ----------------
__global__ void scatter_k(const void* __restrict__ ei, long long E) {
    long long t = (long long)blockIdx.x * blockDim.x + threadIdx.x;
    long long e = t >> 5;
    if (e >= E) return;
    int lane = (int)(t & 31);
    long long s, d;
    if (g_i64flag) {
        const long long* p = (const long long*)ei;
        s = p[e]; d = p[E + e];
    } else {
        const int* p = (const int*)ei;
        s = (long long)p[e]; d = (long long)p[E + e];
    }
    float4 v = ((const float4*)g_x)[s * 32 + lane];
    float* dst = g_hin + d * 128 + lane * 4;
    asm volatile("red.global.add.v4.f32 [%0], {%1, %2, %3, %4};"
                 :: "l"(dst), "f"(v.x), "f"(v.y), "f"(v.z), "f"(v.w) : "memory");
}

// ---------------- tiled SGEMM: C[M,NC] = op(A)[M,K] @ W[K,NC] + bias ----------------
// BNIN: apply y -> relu(y*scale[k]+shift[k]) to A elements on load (k = K index).
template<bool BNIN>
__global__ void __launch_bounds__(256) gemm_k(
    const float* __restrict__ A, const float* __restrict__ W,
    const float* __restrict__ bias, float* __restrict__ C,
    int M, int K, int NC)
{
    __shared__ float As[16][132];
    __shared__ float Bs[16][128];
    const int t  = threadIdx.x;
    const int tx = t & 15;
    const int ty = t >> 4;
    const int bm = blockIdx.x * 128;
    const int bn = blockIdx.y * 128;

    const int arow0 = t >> 2;
    const int arow1 = arow0 + 64;
    const int ak    = (t & 3) * 4;
    const bool av0 = (bm + arow0) < M;
    const bool av1 = (bm + arow1) < M;
    const float* Ap0 = A + (size_t)(bm + arow0) * K + ak;
    const float* Ap1 = A + (size_t)(bm + arow1) * K + ak;

    const int brow0 = t >> 5;
    const int brow1 = brow0 + 8;
    const int bcol  = (t & 31) * 4;
    const float* Wp0 = W + (size_t)brow0 * NC + bn + bcol;
    const float* Wp1 = W + (size_t)brow1 * NC + bn + bcol;

    float acc[8][8];
#pragma unroll
    for (int i = 0; i < 8; i++)
#pragma unroll
        for (int j = 0; j < 8; j++) acc[i][j] = 0.f;

    for (int k0 = 0; k0 < K; k0 += 16) {
        float4 a0 = av0 ? *(const float4*)(Ap0 + k0) : make_float4(0.f, 0.f, 0.f, 0.f);
        float4 a1 = av1 ? *(const float4*)(Ap1 + k0) : make_float4(0.f, 0.f, 0.f, 0.f);
        if (BNIN) {
            int kg = k0 + ak;
            float s0 = g_scale[kg], s1 = g_scale[kg + 1], s2 = g_scale[kg + 2], s3 = g_scale[kg + 3];
            float h0 = g_shift[kg], h1 = g_shift[kg + 1], h2 = g_shift[kg + 2], h3 = g_shift[kg + 3];
            a0.x = fmaxf(fmaf(a0.x, s0, h0), 0.f);
            a0.y = fmaxf(fmaf(a0.y, s1, h1), 0.f);
            a0.z = fmaxf(fmaf(a0.z, s2, h2), 0.f);
            a0.w = fmaxf(fmaf(a0.w, s3, h3), 0.f);
            a1.x = fmaxf(fmaf(a1.x, s0, h0), 0.f);
            a1.y = fmaxf(fmaf(a1.y, s1, h1), 0.f);
            a1.z = fmaxf(fmaf(a1.z, s2, h2), 0.f);
            a1.w = fmaxf(fmaf(a1.w, s3, h3), 0.f);
        }
        float4 b0 = *(const float4*)(Wp0 + (size_t)k0 * NC);
        float4 b1 = *(const float4*)(Wp1 + (size_t)k0 * NC);

        As[ak + 0][arow0] = a0.x; As[ak + 1][arow0] = a0.y;
        As[ak + 2][arow0] = a0.z; As[ak + 3][arow0] = a0.w;
        As[ak + 0][arow1] = a1.x; As[ak + 1][arow1] = a1.y;
        As[ak + 2][arow1] = a1.z; As[ak + 3][arow1] = a1.w;
        *(float4*)&Bs[brow0][bcol] = b0;
        *(float4*)&Bs[brow1][bcol] = b1;
        __syncthreads();

#pragma unroll
        for (int kk = 0; kk < 16; kk++) {
            float ra[8], rb[8];
            *(float4*)(ra)     = *(const float4*)&As[kk][ty * 8];
            *(float4*)(ra + 4) = *(const float4*)&As[kk][ty * 8 + 4];
            *(float4*)(rb)     = *(const float4*)&Bs[kk][tx * 8];
            *(float4*)(rb + 4) = *(const float4*)&Bs[kk][tx * 8 + 4];
#pragma unroll
            for (int i = 0; i < 8; i++)
#pragma unroll
                for (int j = 0; j < 8; j++)
                    acc[i][j] = fmaf(ra[i], rb[j], acc[i][j]);
        }
        __syncthreads();
    }

    float4 bv0 = *(const float4*)(bias + bn + tx * 8);
    float4 bv1 = *(const float4*)(bias + bn + tx * 8 + 4);
#pragma unroll
    for (int i = 0; i < 8; i++) {
        int row = bm + ty * 8 + i;
        if (row < M) {
            float4 o0 = make_float4(acc[i][0] + bv0.x, acc[i][1] + bv0.y,
                                    acc[i][2] + bv0.z, acc[i][3] + bv0.w);
            float4 o1 = make_float4(acc[i][4] + bv1.x, acc[i][5] + bv1.y,
                                    acc[i][6] + bv1.z, acc[i][7] + bv1.w);
            *(float4*)(C + (size_t)row * NC + bn + tx * 8)     = o0;
            *(float4*)(C + (size_t)row * NC + bn + tx * 8 + 4) = o1;
        }
    }
}

// ---------------- per-channel sum / sumsq ----------------
__global__ void stats_k(const float* __restrict__ Y, int M, int C) {
    int t = threadIdx.x;  // blockDim.x == C
    float s = 0.f, q = 0.f;
    for (int r = blockIdx.x; r < M; r += gridDim.x) {
        float v = Y[(size_t)r * C + t];
        s += v; q += v * v;
    }
    atomicAdd(&g_ssum[t], s);
    atomicAdd(&g_ssq[t], q);
}

__global__ void finalize_k(const float* __restrict__ gamma, const float* __restrict__ beta,
                           int C, float invM) {
    int t = threadIdx.x;  // 256 threads always
    if (t < C) {
        float m   = g_ssum[t] * invM;
        float var = g_ssq[t] * invM - m * m;
        float sc  = gamma[t] * rsqrtf(var + 1e-5f);
        g_scale[t] = sc;
        g_shift[t] = beta[t] - m * sc;
    }
    g_ssum[t] = 0.f;
    g_ssq[t]  = 0.f;
}

// ---------------- readout pooling ----------------
__global__ void zero_pool_k() {
    int i = blockIdx.x * blockDim.x + threadIdx.x;
    if (i < GCNT * DD) { g_ps[i] = 0.f; g_pmx[i] = 0.f; }
    if (i < GCNT) g_cnt[i] = 0.f;
}

__global__ void pool_k(const void* __restrict__ batch, int n) {
    long long t = (long long)blockIdx.x * blockDim.x + threadIdx.x;
    long long i = t >> 5;
    if (i >= n) return;
    int lane = (int)(t & 31);
    long long g;
    if (g_i64flag) g = ((const long long*)batch)[i];
    else           g = (long long)((const int*)batch)[i];
    int c = lane * 4;
    float4 v = ((const float4*)g_h2)[i * 32 + lane];
    float r0 = fmaxf(fmaf(v.x, g_scale[c + 0], g_shift[c + 0]), 0.f);
    float r1 = fmaxf(fmaf(v.y, g_scale[c + 1], g_shift[c + 1]), 0.f);
    float r2 = fmaxf(fmaf(v.z, g_scale[c + 2], g_shift[c + 2]), 0.f);
    float r3 = fmaxf(fmaf(v.w, g_scale[c + 3], g_shift[c + 3]), 0.f);
    float* ps = g_ps + g * 128 + c;
    asm volatile("red.global.add.v4.f32 [%0], {%1, %2, %3, %4};"
                 :: "l"(ps), "f"(r0), "f"(r1), "f"(r2), "f"(r3) : "memory");
    unsigned int* mx = (unsigned int*)(g_pmx + g * 128 + c);
    atomicMax(mx + 0, __float_as_uint(r0));  // values >= 0: uint order == float order
    atomicMax(mx + 1, __float_as_uint(r1));
    atomicMax(mx + 2, __float_as_uint(r2));
    atomicMax(mx + 3, __float_as_uint(r3));
    if (lane == 0) atomicAdd(&g_cnt[g], 1.0f);
}

// ---------------- classifier ----------------
__global__ void cgemm1_k(const float* __restrict__ cW1, const float* __restrict__ cb1) {
    int g = blockIdx.x;
    int j = threadIdx.x;  // 128
    __shared__ float z[384];
    float cnt = fmaxf(g_cnt[g], 1.0f);
    float sv = g_ps[g * 128 + j];
    z[j]       = sv;
    z[128 + j] = sv / cnt;
    z[256 + j] = g_pmx[g * 128 + j];
    __syncthreads();
    float acc = cb1[j];
#pragma unroll 8
    for (int k = 0; k < 384; k++)
        acc = fmaf(z[k], cW1[k * 128 + j], acc);
    g_z1[g * 128 + j] = acc;
}

__global__ void cstats_k(const float* __restrict__ cg, const float* __restrict__ cbeta) {
    int j = threadIdx.x;  // 128
    float s = 0.f, q = 0.f;
    for (int g = 0; g < GCNT; g++) {
        float v = g_z1[g * 128 + j];
        s += v; q += v * v;
    }
    float m   = s * (1.0f / GCNT);
    float var = q * (1.0f / GCNT) - m * m;
    float sc  = cg[j] * rsqrtf(var + 1e-5f);
    g_scale[j] = sc;
    g_shift[j] = cbeta[j] - m * sc;
}

__global__ void chead_k(const float* __restrict__ cW2, const float* __restrict__ cb2,
                        const float* __restrict__ cW3, const float* __restrict__ cb3,
                        float* __restrict__ out) {
    int g = blockIdx.x;
    int j = threadIdx.x;  // 64
    __shared__ float a[128];
    __shared__ float z2[64];
    for (int k = j; k < 128; k += 64)
        a[k] = fmaxf(fmaf(g_z1[g * 128 + k], g_scale[k], g_shift[k]), 0.f);
    __syncthreads();
    float acc = cb2[j];
#pragma unroll 8
    for (int k = 0; k < 128; k++)
        acc = fmaf(a[k], cW2[k * 64 + j], acc);
    z2[j] = fmaxf(acc, 0.f);
    __syncthreads();
    if (j < 2) {
        float o = cb3[j];
#pragma unroll 8
        for (int k = 0; k < 64; k++)
            o = fmaf(z2[k], cW3[k * 2 + j], o);
        out[g * 2 + j] = o;
    }
}

// ---------------- launcher ----------------
extern "C" void kernel_launch(void* const* d_in, const int* in_sizes, int n_in,
                              void* d_out, int out_size) {
    const float* x     = (const float*)d_in[0];
    const void*  ei    = d_in[1];
    const void*  batch = d_in[2];
    // num_graphs scalar may or may not be present
    int base = (in_sizes[3] == 1) ? 4 : 3;
    const float* W1    = (const float*)d_in[base + 0];
    const float* b1    = (const float*)d_in[base + 1];
    const float* g1    = (const float*)d_in[base + 2];
    const float* be1   = (const float*)d_in[base + 3];
    const float* W2    = (const float*)d_in[base + 4];
    const float* b2    = (const float*)d_in[base + 5];
    const float* gbn   = (const float*)d_in[base + 6];
    const float* bbn   = (const float*)d_in[base + 7];
    const float* eps   = (const float*)d_in[base + 8];
    const float* cW1   = (const float*)d_in[base + 9];
    const float* cb1   = (const float*)d_in[base + 10];
    const float* cg    = (const float*)d_in[base + 11];
    const float* cbeta = (const float*)d_in[base + 12];
    const float* cW2   = (const float*)d_in[base + 13];
    const float* cb2   = (const float*)d_in[base + 14];
    const float* cW3   = (const float*)d_in[base + 15];
    const float* cb3   = (const float*)d_in[base + 16];

    int n = in_sizes[0] / 128;
    long long E = (long long)in_sizes[1] / 2;
    int n32 = n * 32;
    int nb = (n32 + 255) / 256;
    int gx = (n + 127) / 128;
    long long st = E * 32;
    int sb = (int)((st + 255) / 256);

    float *p_hin, *p_y, *p_h2;
    cudaGetSymbolAddress((void**)&p_hin, g_hin);
    cudaGetSymbolAddress((void**)&p_y,   g_y);
    cudaGetSymbolAddress((void**)&p_h2,  g_h2);

    detect_k<<<1, 1>>>((const unsigned int*)ei);
    prep0_k<<<nb, 256>>>((const float4*)x, eps, n32);

    for (int l = 0; l < 4; l++) {
        if (l > 0) prep_k<<<nb, 256>>>(eps, l, n32);
        scatter_k<<<sb, 256>>>(ei, E);
        gemm_k<false><<<dim3(gx, 2), 256>>>(p_hin, W1 + (size_t)l * 128 * 256,
                                            b1 + l * 256, p_y, n, 128, 256);
        stats_k<<<480, 256>>>(p_y, n, 256);
        finalize_k<<<1, 256>>>(g1 + l * 256, be1 + l * 256, 256, 1.0f / n);
        gemm_k<true><<<dim3(gx, 1), 256>>>(p_y, W2 + (size_t)l * 256 * 128,
                                           b2 + l * 128, p_h2, n, 256, 128);
        stats_k<<<480, 128>>>(p_h2, n, 128);
        finalize_k<<<1, 256>>>(gbn + l * 128, bbn + l * 128, 128, 1.0f / n);
    }

    zero_pool_k<<<256, 256>>>();
    pool_k<<<nb, 256>>>(batch, n);
    cgemm1_k<<<GCNT, 128>>>(cW1, cb1);
    cstats_k<<<1, 128>>>(cg, cbeta);
    chead_k<<<GCNT, 64>>>(cW2, cb2, cW3, cb3, (float*)d_out);
}

// round 2
// speedup vs baseline: 1.3758x; 1.3758x over previous
#include <cuda_runtime.h>
#include <cstdint>
#include <cstddef>

// Problem constants (fixed shapes)
#define NMAX 100000
#define DD   128
#define D2   256
#define GCNT 512

// ---------------- device scratch ----------------
__device__ float g_x  [NMAX * DD];   // current node features
__device__ float g_hin[NMAX * DD];   // (1+eps)*x + aggregation
__device__ float g_y  [NMAX * D2];   // GEMM1 output (pre-BN)
__device__ float g_h2 [NMAX * DD];   // GEMM2 output (pre-BN)
__device__ float g_ssum[D2];
__device__ float g_ssq [D2];
__device__ float g_scale[D2];
__device__ float g_shift[D2];
__device__ float g_ps [GCNT * DD];
__device__ float g_pmx[GCNT * DD];
__device__ float g_cnt[GCNT];
__device__ float g_z1 [GCNT * DD];
__device__ int   g_i64flag;

// ---------------- f32x2 packed math helpers ----------------
__device__ __forceinline__ unsigned long long fma2(unsigned long long a,
                                                   unsigned long long b,
                                                   unsigned long long c) {
    unsigned long long d;
    asm("fma.rn.f32x2 %0, %1, %2, %3;" : "=l"(d) : "l"(a), "l"(b), "l"(c));
    return d;
}
__device__ __forceinline__ unsigned long long packdup(float x) {
    unsigned long long d;
    asm("mov.b64 %0, {%1, %1};" : "=l"(d) : "f"(x));
    return d;
}
__device__ __forceinline__ void unpack2(unsigned long long v, float& lo, float& hi) {
    asm("mov.b64 {%0, %1}, %2;" : "=f"(lo), "=f"(hi) : "l"(v));
}

// ---------------- dtype detection (int32 vs int64 indices) ----------------
__global__ void detect_k(const unsigned int* __restrict__ e) {
    unsigned acc = 0;
    for (int i = 1; i < 128; i += 2) acc |= e[i];
    g_i64flag = (acc == 0u) ? 1 : 0;
}

// ---------------- prep kernels ----------------
__global__ void prep0_k(const float4* __restrict__ x, const float* __restrict__ epsp, int n32) {
    int i = blockIdx.x * blockDim.x + threadIdx.x;
    if (i < n32) {
        float e = 1.0f + epsp[0];
        float4 v = x[i];
        ((float4*)g_x)[i] = v;
        ((float4*)g_hin)[i] = make_float4(v.x * e, v.y * e, v.z * e, v.w * e);
    }
    if (i < D2) { g_ssum[i] = 0.f; g_ssq[i] = 0.f; }
}

// x_cur = relu(bn(h2)); hin = (1+eps_l)*x_cur
__global__ void prep_k(const float* __restrict__ epsp, int l, int n32) {
    int i = blockIdx.x * blockDim.x + threadIdx.x;
    if (i < n32) {
        float e = 1.0f + epsp[l];
        int c = (i & 31) * 4;
        float4 v = ((const float4*)g_h2)[i];
        float4 r;
        r.x = fmaxf(fmaf(v.x, g_scale[c + 0], g_shift[c + 0]), 0.f);
        r.y = fmaxf(fmaf(v.y, g_scale[c + 1], g_shift[c + 1]), 0.f);
        r.z = fmaxf(fmaf(v.z, g_scale[c + 2], g_shift[c + 2]), 0.f);
        r.w = fmaxf(fmaf(v.w, g_scale[c + 3], g_shift[c + 3]), 0.f);
        ((float4*)g_x)[i] = r;
        ((float4*)g_hin)[i] = make_float4(r.x * e, r.y * e, r.z * e, r.w * e);
    }
}

// ---------------- edge scatter-add: hin[dst] += x[src] ----------------
__global__ void scatter_k(const void* __restrict__ ei, long long E) {
    long long t = (long long)blockIdx.x * blockDim.x + threadIdx.x;
    long long e = t >> 5;
    if (e >= E) return;
    int lane = (int)(t & 31);
    long long s, d;
    if (g_i64flag) {
        const long long* p = (const long long*)ei;
        s = p[e]; d = p[E + e];
    } else {
        const int* p = (const int*)ei;
        s = (long long)p[e]; d = (long long)p[E + e];
    }
    float4 v = ((const float4*)g_x)[s * 32 + lane];
    float* dst = g_hin + d * 128 + lane * 4;
    asm volatile("red.global.add.v4.f32 [%0], {%1, %2, %3, %4};"
                 :: "l"(dst), "f"(v.x), "f"(v.y), "f"(v.z), "f"(v.w) : "memory");
}

// ---------------- double-buffered f32x2 SGEMM with fused BN-stats epilogue -----
// C[M,NC] = op(A)[M,K] @ W[K,NC] + bias;  also atomically accumulates per-channel
// sum and sum-of-squares of C into g_ssum / g_ssq.
// BNIN: A elements transformed a -> relu(a*scale[k]+shift[k]) at staging time.
template<bool BNIN>
__global__ void __launch_bounds__(256, 2) gemm_k(
    const float* __restrict__ A, const float* __restrict__ W,
    const float* __restrict__ bias, float* __restrict__ C,
    int M, int K, int NC)
{
    __shared__ float As[2][16][132];
    __shared__ float Bs[2][16][128];
    __shared__ float sred[16][128];

    const int t  = threadIdx.x;
    const int tx = t & 15;
    const int ty = t >> 4;
    const int bm = blockIdx.x * 128;
    const int bn = blockIdx.y * 128;

    const int arow0 = t >> 2;
    const int arow1 = arow0 + 64;
    const int ak    = (t & 3) * 4;
    const bool av0 = (bm + arow0) < M;
    const bool av1 = (bm + arow1) < M;
    const float* Ap0 = A + (size_t)(bm + arow0) * K + ak;
    const float* Ap1 = A + (size_t)(bm + arow1) * K + ak;

    const int brow0 = t >> 5;
    const int brow1 = brow0 + 8;
    const int bcol  = (t & 31) * 4;
    const float* Wp0 = W + (size_t)brow0 * NC + bn + bcol;
    const float* Wp1 = W + (size_t)brow1 * NC + bn + bcol;

    unsigned long long acc2[8][4];
#pragma unroll
    for (int i = 0; i < 8; i++)
#pragma unroll
        for (int j = 0; j < 4; j++) acc2[i][j] = 0ULL;

    float4 a0, a1, b0, b1;

#define LOAD_TILE(K0)                                                          \
    {                                                                          \
        int k0_ = (K0);                                                        \
        a0 = av0 ? *(const float4*)(Ap0 + k0_) : make_float4(0.f,0.f,0.f,0.f); \
        a1 = av1 ? *(const float4*)(Ap1 + k0_) : make_float4(0.f,0.f,0.f,0.f); \
        if (BNIN) {                                                            \
            int kg = k0_ + ak;                                                 \
            float s0 = g_scale[kg],   s1 = g_scale[kg+1];                      \
            float s2 = g_scale[kg+2], s3 = g_scale[kg+3];                      \
            float h0 = g_shift[kg],   h1 = g_shift[kg+1];                      \
            float h2 = g_shift[kg+2], h3 = g_shift[kg+3];                      \
            a0.x = fmaxf(fmaf(a0.x, s0, h0), 0.f);                             \
            a0.y = fmaxf(fmaf(a0.y, s1, h1), 0.f);                             \
            a0.z = fmaxf(fmaf(a0.z, s2, h2), 0.f);                             \
            a0.w = fmaxf(fmaf(a0.w, s3, h3), 0.f);                             \
            a1.x = fmaxf(fmaf(a1.x, s0, h0), 0.f);                             \
            a1.y = fmaxf(fmaf(a1.y, s1, h1), 0.f);                             \
            a1.z = fmaxf(fmaf(a1.z, s2, h2), 0.f);                             \
            a1.w = fmaxf(fmaf(a1.w, s3, h3), 0.f);                             \
        }                                                                      \
        b0 = *(const float4*)(Wp0 + (size_t)k0_ * NC);                         \
        b1 = *(const float4*)(Wp1 + (size_t)k0_ * NC);                         \
    }

#define STORE_TILE(B)                                                          \
    {                                                                          \
        As[B][ak+0][arow0] = a0.x; As[B][ak+1][arow0] = a0.y;                  \
        As[B][ak+2][arow0] = a0.z; As[B][ak+3][arow0] = a0.w;                  \
        As[B][ak+0][arow1] = a1.x; As[B][ak+1][arow1] = a1.y;                  \
        As[B][ak+2][arow1] = a1.z; As[B][ak+3][arow1] = a1.w;                  \
        *(float4*)&Bs[B][brow0][bcol] = b0;                                    \
        *(float4*)&Bs[B][brow1][bcol] = b1;                                    \
    }

    const int steps = K >> 4;
    LOAD_TILE(0);
    STORE_TILE(0);
    __syncthreads();

    int buf = 0;
    for (int s = 0; s < steps; s++) {
        bool has = (s + 1) < steps;
        if (has) LOAD_TILE((s + 1) << 4);

#pragma unroll
        for (int kk = 0; kk < 16; kk++) {
            float4 ra0 = *(const float4*)&As[buf][kk][ty * 8];
            float4 ra1 = *(const float4*)&As[buf][kk][ty * 8 + 4];
            ulonglong2 rbA = *(const ulonglong2*)&Bs[buf][kk][tx * 8];
            ulonglong2 rbB = *(const ulonglong2*)&Bs[buf][kk][tx * 8 + 4];
            float ra[8] = {ra0.x, ra0.y, ra0.z, ra0.w, ra1.x, ra1.y, ra1.z, ra1.w};
#pragma unroll
            for (int i = 0; i < 8; i++) {
                unsigned long long ad = packdup(ra[i]);
                acc2[i][0] = fma2(ad, rbA.x, acc2[i][0]);
                acc2[i][1] = fma2(ad, rbA.y, acc2[i][1]);
                acc2[i][2] = fma2(ad, rbB.x, acc2[i][2]);
                acc2[i][3] = fma2(ad, rbB.y, acc2[i][3]);
            }
        }

        if (has) {
            STORE_TILE(buf ^ 1);
            __syncthreads();
            buf ^= 1;
        }
    }
#undef LOAD_TILE
#undef STORE_TILE

    // ---- epilogue: bias add, write C, per-channel stats ----
    float bv[8];
    *(float4*)(bv)     = *(const float4*)(bias + bn + tx * 8);
    *(float4*)(bv + 4) = *(const float4*)(bias + bn + tx * 8 + 4);

    float cs[8], cq[8];
#pragma unroll
    for (int j = 0; j < 8; j++) { cs[j] = 0.f; cq[j] = 0.f; }

#pragma unroll
    for (int i = 0; i < 8; i++) {
        int row = bm + ty * 8 + i;
        if (row < M) {
            float v[8];
#pragma unroll
            for (int jp = 0; jp < 4; jp++)
                unpack2(acc2[i][jp], v[2 * jp], v[2 * jp + 1]);
#pragma unroll
            for (int j = 0; j < 8; j++) {
                v[j] += bv[j];
                cs[j] += v[j];
                cq[j] = fmaf(v[j], v[j], cq[j]);
            }
            *(float4*)(C + (size_t)row * NC + bn + tx * 8)     = *(float4*)(v);
            *(float4*)(C + (size_t)row * NC + bn + tx * 8 + 4) = *(float4*)(v + 4);
        }
    }

    *(float4*)&sred[ty][tx * 8]     = *(float4*)(cs);
    *(float4*)&sred[ty][tx * 8 + 4] = *(float4*)(cs + 4);
    __syncthreads();
    if (t < 128) {
        float s = 0.f;
#pragma unroll
        for (int r = 0; r < 16; r++) s += sred[r][t];
        atomicAdd(&g_ssum[bn + t], s);
    }
    __syncthreads();
    *(float4*)&sred[ty][tx * 8]     = *(float4*)(cq);
    *(float4*)&sred[ty][tx * 8 + 4] = *(float4*)(cq + 4);
    __syncthreads();
    if (t < 128) {
        float s = 0.f;
#pragma unroll
        for (int r = 0; r < 16; r++) s += sred[r][t];
        atomicAdd(&g_ssq[bn + t], s);
    }
}

__global__ void finalize_k(const float* __restrict__ gamma, const float* __restrict__ beta,
                           int C, float invM) {
    int t = threadIdx.x;  // 256 threads always
    if (t < C) {
        float m   = g_ssum[t] * invM;
        float var = g_ssq[t] * invM - m * m;
        float sc  = gamma[t] * rsqrtf(var + 1e-5f);
        g_scale[t] = sc;
        g_shift[t] = beta[t] - m * sc;
    }
    g_ssum[t] = 0.f;
    g_ssq[t]  = 0.f;
}

// ---------------- readout pooling ----------------
__global__ void zero_pool_k() {
    int i = blockIdx.x * blockDim.x + threadIdx.x;
    if (i < GCNT * DD) { g_ps[i] = 0.f; g_pmx[i] = 0.f; }
    if (i < GCNT) g_cnt[i] = 0.f;
}

__global__ void pool_k(const void* __restrict__ batch, int n) {
    long long t = (long long)blockIdx.x * blockDim.x + threadIdx.x;
    long long i = t >> 5;
    if (i >= n) return;
    int lane = (int)(t & 31);
    long long g;
    if (g_i64flag) g = ((const long long*)batch)[i];
    else           g = (long long)((const int*)batch)[i];
    int c = lane * 4;
    float4 v = ((const float4*)g_h2)[i * 32 + lane];
    float r0 = fmaxf(fmaf(v.x, g_scale[c + 0], g_shift[c + 0]), 0.f);
    float r1 = fmaxf(fmaf(v.y, g_scale[c + 1], g_shift[c + 1]), 0.f);
    float r2 = fmaxf(fmaf(v.z, g_scale[c + 2], g_shift[c + 2]), 0.f);
    float r3 = fmaxf(fmaf(v.w, g_scale[c + 3], g_shift[c + 3]), 0.f);
    float* ps = g_ps + g * 128 + c;
    asm volatile("red.global.add.v4.f32 [%0], {%1, %2, %3, %4};"
                 :: "l"(ps), "f"(r0), "f"(r1), "f"(r2), "f"(r3) : "memory");
    unsigned int* mx = (unsigned int*)(g_pmx + g * 128 + c);
    atomicMax(mx + 0, __float_as_uint(r0));  // values >= 0: uint order == float order
    atomicMax(mx + 1, __float_as_uint(r1));
    atomicMax(mx + 2, __float_as_uint(r2));
    atomicMax(mx + 3, __float_as_uint(r3));
    if (lane == 0) atomicAdd(&g_cnt[g], 1.0f);
}

// ---------------- classifier ----------------
__global__ void cgemm1_k(const float* __restrict__ cW1, const float* __restrict__ cb1) {
    int g = blockIdx.x;
    int j = threadIdx.x;  // 128
    __shared__ float z[384];
    float cnt = fmaxf(g_cnt[g], 1.0f);
    float sv = g_ps[g * 128 + j];
    z[j]       = sv;
    z[128 + j] = sv / cnt;
    z[256 + j] = g_pmx[g * 128 + j];
    __syncthreads();
    float acc = cb1[j];
#pragma unroll 8
    for (int k = 0; k < 384; k++)
        acc = fmaf(z[k], cW1[k * 128 + j], acc);
    g_z1[g * 128 + j] = acc;
}

__global__ void cstats_k(const float* __restrict__ cg, const float* __restrict__ cbeta) {
    int j = threadIdx.x;  // 128
    float s = 0.f, q = 0.f;
    for (int g = 0; g < GCNT; g++) {
        float v = g_z1[g * 128 + j];
        s += v; q += v * v;
    }
    float m   = s * (1.0f / GCNT);
    float var = q * (1.0f / GCNT) - m * m;
    float sc  = cg[j] * rsqrtf(var + 1e-5f);
    g_scale[j] = sc;
    g_shift[j] = cbeta[j] - m * sc;
}

__global__ void chead_k(const float* __restrict__ cW2, const float* __restrict__ cb2,
                        const float* __restrict__ cW3, const float* __restrict__ cb3,
                        float* __restrict__ out) {
    int g = blockIdx.x;
    int j = threadIdx.x;  // 64
    __shared__ float a[128];
    __shared__ float z2[64];
    for (int k = j; k < 128; k += 64)
        a[k] = fmaxf(fmaf(g_z1[g * 128 + k], g_scale[k], g_shift[k]), 0.f);
    __syncthreads();
    float acc = cb2[j];
#pragma unroll 8
    for (int k = 0; k < 128; k++)
        acc = fmaf(a[k], cW2[k * 64 + j], acc);
    z2[j] = fmaxf(acc, 0.f);
    __syncthreads();
    if (j < 2) {
        float o = cb3[j];
#pragma unroll 8
        for (int k = 0; k < 64; k++)
            o = fmaf(z2[k], cW3[k * 2 + j], o);
        out[g * 2 + j] = o;
    }
}

// ---------------- launcher ----------------
extern "C" void kernel_launch(void* const* d_in, const int* in_sizes, int n_in,
                              void* d_out, int out_size) {
    const float* x     = (const float*)d_in[0];
    const void*  ei    = d_in[1];
    const void*  batch = d_in[2];
    // num_graphs scalar may or may not be present
    int base = (in_sizes[3] == 1) ? 4 : 3;
    const float* W1    = (const float*)d_in[base + 0];
    const float* b1    = (const float*)d_in[base + 1];
    const float* g1    = (const float*)d_in[base + 2];
    const float* be1   = (const float*)d_in[base + 3];
    const float* W2    = (const float*)d_in[base + 4];
    const float* b2    = (const float*)d_in[base + 5];
    const float* gbn   = (const float*)d_in[base + 6];
    const float* bbn   = (const float*)d_in[base + 7];
    const float* eps   = (const float*)d_in[base + 8];
    const float* cW1   = (const float*)d_in[base + 9];
    const float* cb1   = (const float*)d_in[base + 10];
    const float* cg    = (const float*)d_in[base + 11];
    const float* cbeta = (const float*)d_in[base + 12];
    const float* cW2   = (const float*)d_in[base + 13];
    const float* cb2   = (const float*)d_in[base + 14];
    const float* cW3   = (const float*)d_in[base + 15];
    const float* cb3   = (const float*)d_in[base + 16];

    int n = in_sizes[0] / 128;
    long long E = (long long)in_sizes[1] / 2;
    int n32 = n * 32;
    int nb = (n32 + 255) / 256;
    int gx = (n + 127) / 128;
    long long st = E * 32;
    int sb = (int)((st + 255) / 256);

    float *p_hin, *p_y, *p_h2;
    cudaGetSymbolAddress((void**)&p_hin, g_hin);
    cudaGetSymbolAddress((void**)&p_y,   g_y);
    cudaGetSymbolAddress((void**)&p_h2,  g_h2);

    detect_k<<<1, 1>>>((const unsigned int*)ei);
    prep0_k<<<nb, 256>>>((const float4*)x, eps, n32);

    for (int l = 0; l < 4; l++) {
        if (l > 0) prep_k<<<nb, 256>>>(eps, l, n32);
        scatter_k<<<sb, 256>>>(ei, E);
        gemm_k<false><<<dim3(gx, 2), 256>>>(p_hin, W1 + (size_t)l * 128 * 256,
                                            b1 + l * 256, p_y, n, 128, 256);
        finalize_k<<<1, 256>>>(g1 + l * 256, be1 + l * 256, 256, 1.0f / n);
        gemm_k<true><<<dim3(gx, 1), 256>>>(p_y, W2 + (size_t)l * 256 * 128,
                                           b2 + l * 128, p_h2, n, 256, 128);
        finalize_k<<<1, 256>>>(gbn + l * 128, bbn + l * 128, 128, 1.0f / n);
    }

    zero_pool_k<<<256, 256>>>();
    pool_k<<<nb, 256>>>(batch, n);
    cgemm1_k<<<GCNT, 128>>>(cW1, cb1);
    cstats_k<<<1, 128>>>(cg, cbeta);
    chead_k<<<GCNT, 64>>>(cW2, cb2, cW3, cb3, (float*)d_out);
}

// round 4
// speedup vs baseline: 1.7876x; 1.2993x over previous
#include <cuda_runtime.h>
#include <cuda_bf16.h>
#include <cstdint>
#include <cstddef>

// Problem constants (fixed shapes)
#define NMAX 100000
#define GCNT 512
#define NLAYER 4

// tcgen05 only exists in the arch-specific (sm_103a) device pass.
#if defined(__CUDA_ARCH__) && defined(__CUDA_ARCH_FEAT_SM103_ALL)
#define HAS_TC 1
#else
#define HAS_TC 0
#endif

// ---------------- device scratch ----------------
__device__ float g_x  [NMAX * 128];
__device__ float g_hin[NMAX * 128];
__device__ float g_y  [NMAX * 256];
__device__ float g_h2 [NMAX * 128];
__device__ float g_ssum[256];
__device__ float g_ssq [256];
__device__ float g_scale[256];
__device__ float g_shift[256];
__device__ float g_ps [GCNT * 128];
__device__ float g_pmx[GCNT * 128];
__device__ float g_cnt[GCNT];
__device__ float g_z1 [GCNT * 128];
__device__ int   g_i64flag;

// pre-split weights, B layout: [layer][n(out)][k(in)] bf16, K-major rows
__device__ __nv_bfloat16 g_b1hi[NLAYER * 256 * 128];
__device__ __nv_bfloat16 g_b1lo[NLAYER * 256 * 128];
__device__ __nv_bfloat16 g_b2hi[NLAYER * 128 * 256];
__device__ __nv_bfloat16 g_b2lo[NLAYER * 128 * 256];

// ---------------- PTX helpers ----------------
__device__ __forceinline__ uint32_t smem_u32(const void* p) {
    uint32_t a;
    asm("{ .reg .u64 t; cvta.to.shared.u64 t, %1; cvt.u32.u64 %0, t; }" : "=r"(a) : "l"(p));
    return a;
}
__device__ __forceinline__ uint32_t elect_one() {
    uint32_t p;
    asm volatile("{ .reg .pred p; elect.sync _|p, 0xFFFFFFFF; selp.b32 %0, 1, 0, p; }" : "=r"(p));
    return p;
}
#define SW128(o) ((o) ^ (((o) >> 3) & 0x70))
static __device__ __forceinline__ uint64_t make_desc(uint32_t addr) {
    // SW128, version=1 (Blackwell), SBO=64, LBO=1
    return ((uint64_t)2 << 61) | ((uint64_t)1 << 46) | ((uint64_t)64 << 32) |
           ((uint64_t)1 << 16) | ((uint64_t)(addr >> 4) & 0x3FFF);
}

#if HAS_TC
__device__ __forceinline__ void mma_bf16_ss(uint32_t d, uint64_t a, uint64_t b,
                                            uint32_t idesc, uint32_t en) {
    asm volatile(
        "{\n\t.reg .pred p;\n\tsetp.ne.u32 p, %4, 0;\n\t"
        "tcgen05.mma.cta_group::1.kind::f16 [%0], %1, %2, %3, {%5, %5, %5, %5}, p;\n\t}"
        :: "r"(d), "l"(a), "l"(b), "r"(idesc), "r"(en), "r"(0u) : "memory");
}
#define TC_ALLOC(sm, n)  asm volatile("tcgen05.alloc.cta_group::1.sync.aligned.shared::cta.b32 [%0], %1;" :: "r"(sm), "r"((uint32_t)(n)) : "memory")
#define TC_DEALLOC(t, n) asm volatile("tcgen05.dealloc.cta_group::1.sync.aligned.b32 %0, %1;" :: "r"(t), "r"((uint32_t)(n)))
#define TC_COMMIT(mb)    asm volatile("tcgen05.commit.cta_group::1.mbarrier::arrive::one.shared::cluster.b64 [%0];" :: "r"(mb) : "memory")
#define TC_FENCE_AFTER() asm volatile("tcgen05.fence::after_thread_sync;" ::: "memory")
#define TC_FENCE_BEFORE() asm volatile("tcgen05.fence::before_thread_sync;" ::: "memory")
#define TC_WAIT_LD()     asm volatile("tcgen05.wait::ld.sync.aligned;" ::: "memory")
#define LDTM32(r, a)                                                            \
    asm volatile("tcgen05.ld.sync.aligned.32x32b.x32.b32 "                      \
        "{%0,%1,%2,%3,%4,%5,%6,%7,%8,%9,%10,%11,%12,%13,%14,%15,"               \
        "%16,%17,%18,%19,%20,%21,%22,%23,%24,%25,%26,%27,%28,%29,%30,%31}, [%32];" \
        : "=r"((r)[0]),"=r"((r)[1]),"=r"((r)[2]),"=r"((r)[3]),                  \
          "=r"((r)[4]),"=r"((r)[5]),"=r"((r)[6]),"=r"((r)[7]),                  \
          "=r"((r)[8]),"=r"((r)[9]),"=r"((r)[10]),"=r"((r)[11]),                \
          "=r"((r)[12]),"=r"((r)[13]),"=r"((r)[14]),"=r"((r)[15]),              \
          "=r"((r)[16]),"=r"((r)[17]),"=r"((r)[18]),"=r"((r)[19]),              \
          "=r"((r)[20]),"=r"((r)[21]),"=r"((r)[22]),"=r"((r)[23]),              \
          "=r"((r)[24]),"=r"((r)[25]),"=r"((r)[26]),"=r"((r)[27]),              \
          "=r"((r)[28]),"=r"((r)[29]),"=r"((r)[30]),"=r"((r)[31])               \
        : "r"(a))
#else
// compute_103 (non-'a') pass: stubs. Never executed (sm_103a cubin selected).
__device__ __forceinline__ void mma_bf16_ss(uint32_t, uint64_t, uint64_t, uint32_t, uint32_t) {}
#define TC_ALLOC(sm, n)   ((void)0)
#define TC_DEALLOC(t, n)  ((void)0)
#define TC_COMMIT(mb)     ((void)0)
#define TC_FENCE_AFTER()  ((void)0)
#define TC_FENCE_BEFORE() ((void)0)
#define TC_WAIT_LD()      ((void)0)
#define LDTM32(r, a)      do { _Pragma("unroll") for (int _i = 0; _i < 32; _i++) (r)[_i] = 0u; } while (0)
#endif

#define MB_INIT(mb, c)   asm volatile("mbarrier.init.shared.b64 [%0], %1;" :: "r"(mb), "r"((uint32_t)(c)) : "memory")
#define MB_INVAL(mb)     asm volatile("mbarrier.inval.shared.b64 [%0];" :: "r"(mb) : "memory")
#define FENCE_ASYNC()    asm volatile("fence.proxy.async.shared::cta;" ::: "memory")

#if HAS_TC
#define MB_WAIT(mb, par) do {                                                   \
    uint32_t _m = (mb), _p = (par), _d;                                         \
    asm volatile("{ .reg .pred p; mbarrier.try_wait.parity.acquire.cta.shared::cta.b64 p, [%1], %2; selp.b32 %0, 1, 0, p; }" \
                 : "=r"(_d) : "r"(_m), "r"(_p) : "memory");                     \
    if (!_d) {                                                                  \
        asm volatile("{ .reg .pred P1; W%=: mbarrier.try_wait.parity.acquire.cta.shared::cta.b64 P1, [%0], %1, 0x989680; @P1 bra.uni D%=; bra.uni W%=; D%=: }" \
                     :: "r"(_m), "r"(_p) : "memory");                           \
    }                                                                           \
} while (0)
#else
#define MB_WAIT(mb, par) ((void)0)
#endif

// ---------------- dtype detection (int32 vs int64 indices) ----------------
__global__ void detect_k(const unsigned int* __restrict__ e) {
    unsigned acc = 0;
    for (int i = 1; i < 128; i += 2) acc |= e[i];
    g_i64flag = (acc == 0u) ? 1 : 0;
}

// ---------------- weight split fp32 -> bf16 hi/lo ----------------
__global__ void wconv_k(const float* __restrict__ W1, const float* __restrict__ W2) {
    int i = blockIdx.x * 256 + threadIdx.x;
    const int tot = NLAYER * 256 * 128;
    if (i >= tot) return;
    int l = i / (256 * 128), rem = i % (256 * 128);
    // W1: [l][k(128)][n(256)] -> B1 [l][n][k]
    {
        int n = rem / 128, k = rem % 128;
        float w = W1[l * 32768 + k * 256 + n];
        __nv_bfloat16 h = __float2bfloat16(w);
        g_b1hi[i] = h;
        g_b1lo[i] = __float2bfloat16(w - __bfloat162float(h));
    }
    // W2: [l][k(256)][n(128)] -> B2 [l][n][k]
    {
        int n = rem / 256, k = rem % 256;
        float w = W2[l * 32768 + k * 128 + n];
        __nv_bfloat16 h = __float2bfloat16(w);
        g_b2hi[i] = h;
        g_b2lo[i] = __float2bfloat16(w - __bfloat162float(h));
    }
}

// ---------------- prep kernels ----------------
__global__ void prep0_k(const float4* __restrict__ x, const float* __restrict__ epsp, int n32) {
    int i = blockIdx.x * blockDim.x + threadIdx.x;
    if (i < n32) {
        float e = 1.0f + epsp[0];
        float4 v = x[i];
        ((float4*)g_x)[i] = v;
        ((float4*)g_hin)[i] = make_float4(v.x * e, v.y * e, v.z * e, v.w * e);
    }
    if (i < 256) { g_ssum[i] = 0.f; g_ssq[i] = 0.f; }
}

__global__ void prep_k(const float* __restrict__ epsp, int l, int n32) {
    int i = blockIdx.x * blockDim.x + threadIdx.x;
    if (i < n32) {
        float e = 1.0f + epsp[l];
        int c = (i & 31) * 4;
        float4 v = ((const float4*)g_h2)[i];
        float4 r;
        r.x = fmaxf(fmaf(v.x, g_scale[c + 0], g_shift[c + 0]), 0.f);
        r.y = fmaxf(fmaf(v.y, g_scale[c + 1], g_shift[c + 1]), 0.f);
        r.z = fmaxf(fmaf(v.z, g_scale[c + 2], g_shift[c + 2]), 0.f);
        r.w = fmaxf(fmaf(v.w, g_scale[c + 3], g_shift[c + 3]), 0.f);
        ((float4*)g_x)[i] = r;
        ((float4*)g_hin)[i] = make_float4(r.x * e, r.y * e, r.z * e, r.w * e);
    }
}

// ---------------- edge scatter-add: hin[dst] += x[src] ----------------
__global__ void scatter_k(const void* __restrict__ ei, long long E) {
    long long t = (long long)blockIdx.x * blockDim.x + threadIdx.x;
    long long e = t >> 5;
    if (e >= E) return;
    int lane = (int)(t & 31);
    long long s, d;
    if (g_i64flag) {
        const long long* p = (const long long*)ei;
        s = p[e]; d = p[E + e];
    } else {
        const int* p = (const int*)ei;
        s = (long long)p[e]; d = (long long)p[E + e];
    }
    float4 v = ((const float4*)g_x)[s * 32 + lane];
    float* dst = g_hin + d * 128 + lane * 4;
    asm volatile("red.global.add.v4.f32 [%0], {%1, %2, %3, %4};"
                 :: "l"(dst), "f"(v.x), "f"(v.y), "f"(v.z), "f"(v.w) : "memory");
}

// ============ tcgen05 bf16x3 GEMM with fused BN-stats ============
// C[M,NC] = op(A)[M,K] @ W[K,NC] + bias ; per-128-col tile per CTA.
// B pre-split bf16 hi/lo in global, layout [n][k] (D = A @ B^T).
// BNIN: a -> relu(a*g_scale[k]+g_shift[k]) before split.
#define SOFF_PTR  0
#define SOFF_MBAR 16
#define T_AHI 1024
#define T_ALO 17408
#define T_BHI 33792
#define T_BLO 50176
#define TG_SMEM 67584
// idesc kind::f16: dtype=F32(1<<4), atype=BF16(1<<7), btype=BF16(1<<10),
// N=128 (16<<17), M=128 (8<<24)
#define TG_IDESC 0x8200490u

__device__ __forceinline__ uint32_t pack_bf16x2(float a, float b) {
    __nv_bfloat162 h = __float22bfloat162_rn(make_float2(a, b));
    return *reinterpret_cast<uint32_t*>(&h);
}

template<bool BNIN>
__global__ void __launch_bounds__(256, 2) tgemm_k(
    const float* __restrict__ A,
    const __nv_bfloat16* __restrict__ Bhi, const __nv_bfloat16* __restrict__ Blo,
    const float* __restrict__ bias, float* __restrict__ C,
    int M, int K, int NC)
{
    extern __shared__ char smem[];
    const uint32_t sb = smem_u32(smem);
    const int t = threadIdx.x, wid = t >> 5, lid = t & 31;
    const int bm = blockIdx.x * 128, bn = blockIdx.y * 128;

    if (wid == 0) TC_ALLOC(sb + SOFF_PTR, 128);
    if (t == 0) MB_INIT(sb + SOFF_MBAR, 1);
    __syncthreads();
    uint32_t tmem;
    asm volatile("ld.shared.b32 %0, [%1];" : "=r"(tmem) : "r"(sb + SOFF_PTR));

    const uint64_t dAhi = make_desc(sb + T_AHI);
    const uint64_t dAlo = make_desc(sb + T_ALO);
    const uint64_t dBhi = make_desc(sb + T_BHI);
    const uint64_t dBlo = make_desc(sb + T_BLO);
    const int nch = K >> 6;

    for (int ch = 0; ch < nch; ch++) {
        const int kbase = ch * 64;
#pragma unroll
        for (int it = 0; it < 4; it++) {
            int idx = t + it * 256;        // 0..1023
            int row = idx >> 3;            // 0..127
            int kg  = idx & 7;             // 16B group (8 k-values)
            uint32_t so = SW128((uint32_t)(row * 128 + kg * 16));
            // B (weights, already bf16)
            size_t boff = (size_t)(bn + row) * K + kbase + kg * 8;
            *(uint4*)(smem + T_BHI + so) = *(const uint4*)(Bhi + boff);
            *(uint4*)(smem + T_BLO + so) = *(const uint4*)(Blo + boff);
            // A (fp32 -> bf16 hi/lo split)
            int grow = bm + row;
            uint4 ah = make_uint4(0, 0, 0, 0), al = make_uint4(0, 0, 0, 0);
            if (grow < M) {
                const float* ap = A + (size_t)grow * K + kbase + kg * 8;
                float f[8];
                *(float4*)(f)     = *(const float4*)ap;
                *(float4*)(f + 4) = *(const float4*)(ap + 4);
                if (BNIN) {
                    int cb = kbase + kg * 8;
#pragma unroll
                    for (int j = 0; j < 8; j++)
                        f[j] = fmaxf(fmaf(f[j], g_scale[cb + j], g_shift[cb + j]), 0.f);
                }
                uint32_t h[4], lo[4];
#pragma unroll
                for (int j = 0; j < 4; j++) {
                    h[j] = pack_bf16x2(f[2 * j], f[2 * j + 1]);
                    __nv_bfloat162 hb = *reinterpret_cast<__nv_bfloat162*>(&h[j]);
                    float2 hr = __bfloat1622float2(hb);
                    lo[j] = pack_bf16x2(f[2 * j] - hr.x, f[2 * j + 1] - hr.y);
                }
                ah = make_uint4(h[0], h[1], h[2], h[3]);
                al = make_uint4(lo[0], lo[1], lo[2], lo[3]);
            }
            *(uint4*)(smem + T_AHI + so) = ah;
            *(uint4*)(smem + T_ALO + so) = al;
        }
        FENCE_ASYNC();
        __syncthreads();
        if (wid == 0 && elect_one()) {
#pragma unroll
            for (int s = 0; s < 4; s++)
                mma_bf16_ss(tmem, dAhi + s * 2, dBhi + s * 2, TG_IDESC,
                            (ch == 0 && s == 0) ? 0u : 1u);
#pragma unroll
            for (int s = 0; s < 4; s++)
                mma_bf16_ss(tmem, dAhi + s * 2, dBlo + s * 2, TG_IDESC, 1u);
#pragma unroll
            for (int s = 0; s < 4; s++)
                mma_bf16_ss(tmem, dAlo + s * 2, dBhi + s * 2, TG_IDESC, 1u);
            TC_COMMIT(sb + SOFF_MBAR);
        }
        __syncthreads();
        MB_WAIT(sb + SOFF_MBAR, ch & 1);
    }
    TC_FENCE_AFTER();

    // ---- epilogue: bias, store C, stash rows in smem for stats ----
    float* buf = reinterpret_cast<float*>(smem + 1024);   // [128][129]
    if (wid < 4) {
        int row = wid * 32 + lid;
        int grow = bm + row;
#pragma unroll
        for (int b = 0; b < 4; b++) {
            uint32_t r[32];
            LDTM32(r, tmem + b * 32);
            TC_WAIT_LD();
            float v[32];
#pragma unroll
            for (int i = 0; i < 32; i++)
                v[i] = __uint_as_float(r[i]) + bias[bn + b * 32 + i];
            if (grow < M) {
#pragma unroll
                for (int q = 0; q < 8; q++)
                    *(float4*)(C + (size_t)grow * NC + bn + b * 32 + q * 4) = *(float4*)(v + q * 4);
            }
#pragma unroll
            for (int i = 0; i < 32; i++)
                buf[row * 129 + b * 32 + i] = v[i];
        }
        TC_FENCE_BEFORE();
    }
    __syncthreads();

    // ---- column stats: thread (c, h) sums rows [h*64, h*64+64) ----
    {
        int c = t & 127, h = t >> 7;
        float s = 0.f, q = 0.f;
#pragma unroll 8
        for (int rr = 0; rr < 64; rr++) {
            int r = h * 64 + rr;
            if (bm + r < M) {
                float v = buf[r * 129 + c];
                s += v;
                q = fmaf(v, v, q);
            }
        }
        atomicAdd(&g_ssum[bn + c], s);
        atomicAdd(&g_ssq[bn + c], q);
    }
    __syncthreads();
    if (t == 0) MB_INVAL(sb + SOFF_MBAR);
    if (wid == 0) TC_DEALLOC(tmem, 128);
}

__global__ void finalize_k(const float* __restrict__ gamma, const float* __restrict__ beta,
                           int C, float invM) {
    int t = threadIdx.x;  // 256
    if (t < C) {
        float m   = g_ssum[t] * invM;
        float var = g_ssq[t] * invM - m * m;
        float sc  = gamma[t] * rsqrtf(var + 1e-5f);
        g_scale[t] = sc;
        g_shift[t] = beta[t] - m * sc;
    }
    g_ssum[t] = 0.f;
    g_ssq[t]  = 0.f;
}

// ---------------- readout pooling ----------------
__global__ void zero_pool_k() {
    int i = blockIdx.x * blockDim.x + threadIdx.x;
    if (i < GCNT * 128) { g_ps[i] = 0.f; g_pmx[i] = 0.f; }
    if (i < GCNT) g_cnt[i] = 0.f;
}

__global__ void pool_k(const void* __restrict__ batch, int n) {
    long long t = (long long)blockIdx.x * blockDim.x + threadIdx.x;
    long long i = t >> 5;
    if (i >= n) return;
    int lane = (int)(t & 31);
    long long g;
    if (g_i64flag) g = ((const long long*)batch)[i];
    else           g = (long long)((const int*)batch)[i];
    int c = lane * 4;
    float4 v = ((const float4*)g_h2)[i * 32 + lane];
    float r0 = fmaxf(fmaf(v.x, g_scale[c + 0], g_shift[c + 0]), 0.f);
    float r1 = fmaxf(fmaf(v.y, g_scale[c + 1], g_shift[c + 1]), 0.f);
    float r2 = fmaxf(fmaf(v.z, g_scale[c + 2], g_shift[c + 2]), 0.f);
    float r3 = fmaxf(fmaf(v.w, g_scale[c + 3], g_shift[c + 3]), 0.f);
    float* ps = g_ps + g * 128 + c;
    asm volatile("red.global.add.v4.f32 [%0], {%1, %2, %3, %4};"
                 :: "l"(ps), "f"(r0), "f"(r1), "f"(r2), "f"(r3) : "memory");
    unsigned int* mx = (unsigned int*)(g_pmx + g * 128 + c);
    atomicMax(mx + 0, __float_as_uint(r0));
    atomicMax(mx + 1, __float_as_uint(r1));
    atomicMax(mx + 2, __float_as_uint(r2));
    atomicMax(mx + 3, __float_as_uint(r3));
    if (lane == 0) atomicAdd(&g_cnt[g], 1.0f);
}

// ---------------- classifier ----------------
__global__ void cgemm1_k(const float* __restrict__ cW1, const float* __restrict__ cb1) {
    int g = blockIdx.x;
    int j = threadIdx.x;  // 128
    __shared__ float z[384];
    float cnt = fmaxf(g_cnt[g], 1.0f);
    float sv = g_ps[g * 128 + j];
    z[j]       = sv;
    z[128 + j] = sv / cnt;
    z[256 + j] = g_pmx[g * 128 + j];
    __syncthreads();
    float acc = cb1[j];
#pragma unroll 8
    for (int k = 0; k < 384; k++)
        acc = fmaf(z[k], cW1[k * 128 + j], acc);
    g_z1[g * 128 + j] = acc;
}

__global__ void cstats_k(const float* __restrict__ cg, const float* __restrict__ cbeta) {
    int j = threadIdx.x;  // 128
    float s = 0.f, q = 0.f;
    for (int g = 0; g < GCNT; g++) {
        float v = g_z1[g * 128 + j];
        s += v; q += v * v;
    }
    float m   = s * (1.0f / GCNT);
    float var = q * (1.0f / GCNT) - m * m;
    float sc  = cg[j] * rsqrtf(var + 1e-5f);
    g_scale[j] = sc;
    g_shift[j] = cbeta[j] - m * sc;
}

__global__ void chead_k(const float* __restrict__ cW2, const float* __restrict__ cb2,
                        const float* __restrict__ cW3, const float* __restrict__ cb3,
                        float* __restrict__ out) {
    int g = blockIdx.x;
    int j = threadIdx.x;  // 64
    __shared__ float a[128];
    __shared__ float z2[64];
    for (int k = j; k < 128; k += 64)
        a[k] = fmaxf(fmaf(g_z1[g * 128 + k], g_scale[k], g_shift[k]), 0.f);
    __syncthreads();
    float acc = cb2[j];
#pragma unroll 8
    for (int k = 0; k < 128; k++)
        acc = fmaf(a[k], cW2[k * 64 + j], acc);
    z2[j] = fmaxf(acc, 0.f);
    __syncthreads();
    if (j < 2) {
        float o = cb3[j];
#pragma unroll 8
        for (int k = 0; k < 64; k++)
            o = fmaf(z2[k], cW3[k * 2 + j], o);
        out[g * 2 + j] = o;
    }
}

// ---------------- launcher ----------------
extern "C" void kernel_launch(void* const* d_in, const int* in_sizes, int n_in,
                              void* d_out, int out_size) {
    const float* x     = (const float*)d_in[0];
    const void*  ei    = d_in[1];
    const void*  batch = d_in[2];
    int base = (in_sizes[3] == 1) ? 4 : 3;
    const float* W1    = (const float*)d_in[base + 0];
    const float* b1    = (const float*)d_in[base + 1];
    const float* g1    = (const float*)d_in[base + 2];
    const float* be1   = (const float*)d_in[base + 3];
    const float* W2    = (const float*)d_in[base + 4];
    const float* b2    = (const float*)d_in[base + 5];
    const float* gbn   = (const float*)d_in[base + 6];
    const float* bbn   = (const float*)d_in[base + 7];
    const float* eps   = (const float*)d_in[base + 8];
    const float* cW1   = (const float*)d_in[base + 9];
    const float* cb1   = (const float*)d_in[base + 10];
    const float* cg    = (const float*)d_in[base + 11];
    const float* cbeta = (const float*)d_in[base + 12];
    const float* cW2   = (const float*)d_in[base + 13];
    const float* cb2   = (const float*)d_in[base + 14];
    const float* cW3   = (const float*)d_in[base + 15];
    const float* cb3   = (const float*)d_in[base + 16];

    int n = in_sizes[0] / 128;
    long long E = (long long)in_sizes[1] / 2;
    int n32 = n * 32;
    int nb = (n32 + 255) / 256;
    int gx = (n + 127) / 128;
    long long st = E * 32;
    int sb = (int)((st + 255) / 256);

    static int smem_set = 0;
    if (!smem_set) {
        cudaFuncSetAttribute(tgemm_k<false>, cudaFuncAttributeMaxDynamicSharedMemorySize, TG_SMEM);
        cudaFuncSetAttribute(tgemm_k<true>,  cudaFuncAttributeMaxDynamicSharedMemorySize, TG_SMEM);
        smem_set = 1;
    }

    float *p_hin, *p_y, *p_h2;
    __nv_bfloat16 *p_b1hi, *p_b1lo, *p_b2hi, *p_b2lo;
    cudaGetSymbolAddress((void**)&p_hin, g_hin);
    cudaGetSymbolAddress((void**)&p_y,   g_y);
    cudaGetSymbolAddress((void**)&p_h2,  g_h2);
    cudaGetSymbolAddress((void**)&p_b1hi, g_b1hi);
    cudaGetSymbolAddress((void**)&p_b1lo, g_b1lo);
    cudaGetSymbolAddress((void**)&p_b2hi, g_b2hi);
    cudaGetSymbolAddress((void**)&p_b2lo, g_b2lo);

    detect_k<<<1, 1>>>((const unsigned int*)ei);
    wconv_k<<<(NLAYER * 256 * 128 + 255) / 256, 256>>>(W1, W2);
    prep0_k<<<nb, 256>>>((const float4*)x, eps, n32);

    for (int l = 0; l < 4; l++) {
        if (l > 0) prep_k<<<nb, 256>>>(eps, l, n32);
        scatter_k<<<sb, 256>>>(ei, E);
        tgemm_k<false><<<dim3(gx, 2), 256, TG_SMEM>>>(
            p_hin, p_b1hi + (size_t)l * 32768, p_b1lo + (size_t)l * 32768,
            b1 + l * 256, p_y, n, 128, 256);
        finalize_k<<<1, 256>>>(g1 + l * 256, be1 + l * 256, 256, 1.0f / n);
        tgemm_k<true><<<dim3(gx, 1), 256, TG_SMEM>>>(
            p_y, p_b2hi + (size_t)l * 32768, p_b2lo + (size_t)l * 32768,
            b2 + l * 128, p_h2, n, 256, 128);
        finalize_k<<<1, 256>>>(gbn + l * 128, bbn + l * 128, 128, 1.0f / n);
    }

    zero_pool_k<<<256, 256>>>();
    pool_k<<<nb, 256>>>(batch, n);
    cgemm1_k<<<GCNT, 128>>>(cW1, cb1);
    cstats_k<<<1, 128>>>(cg, cbeta);
    chead_k<<<GCNT, 64>>>(cW2, cb2, cW3, cb3, (float*)d_out);
}

// round 5
// speedup vs baseline: 2.1660x; 1.2117x over previous
#include <cuda_runtime.h>
#include <cuda_bf16.h>
#include <cstdint>
#include <cstddef>

// Problem constants (fixed shapes)
#define NMAX 100000
#define GCNT 512
#define NLAYER 4

// tcgen05 only exists in the arch-specific (sm_103a) device pass.
#if defined(__CUDA_ARCH__) && defined(__CUDA_ARCH_FEAT_SM103_ALL)
#define HAS_TC 1
#else
#define HAS_TC 0
#endif

// ---------------- device scratch ----------------
__device__ float g_hin[NMAX * 128];
__device__ float g_y  [NMAX * 256];
__device__ float g_h2 [NMAX * 128];
__device__ float g_ssum [256];   // stats of y  (inner BN)
__device__ float g_ssq  [256];
__device__ float g_ssum2[128];   // stats of h2 (outer BN)
__device__ float g_ssq2 [128];
__device__ float g_scale[256];   // outer BN affine (also reused by classifier)
__device__ float g_shift[256];
__device__ float g_ps [GCNT * 128];
__device__ float g_pmx[GCNT * 128];
__device__ float g_cnt[GCNT];
__device__ float g_z1 [GCNT * 128];
__device__ int   g_i64flag;

// pre-split weights, B layout: [layer][n(out)][k(in)] bf16, K-major rows
__device__ __nv_bfloat16 g_b1hi[NLAYER * 256 * 128];
__device__ __nv_bfloat16 g_b1lo[NLAYER * 256 * 128];
__device__ __nv_bfloat16 g_b2hi[NLAYER * 128 * 256];
__device__ __nv_bfloat16 g_b2lo[NLAYER * 128 * 256];

// ---------------- PTX helpers ----------------
__device__ __forceinline__ uint32_t smem_u32(const void* p) {
    uint32_t a;
    asm("{ .reg .u64 t; cvta.to.shared.u64 t, %1; cvt.u32.u64 %0, t; }" : "=r"(a) : "l"(p));
    return a;
}
__device__ __forceinline__ uint32_t elect_one() {
    uint32_t p;
    asm volatile("{ .reg .pred p; elect.sync _|p, 0xFFFFFFFF; selp.b32 %0, 1, 0, p; }" : "=r"(p));
    return p;
}
#define SW128(o) ((o) ^ (((o) >> 3) & 0x70))
static __device__ __forceinline__ uint64_t make_desc(uint32_t addr) {
    // SW128, version=1 (Blackwell), SBO=64, LBO=1
    return ((uint64_t)2 << 61) | ((uint64_t)1 << 46) | ((uint64_t)64 << 32) |
           ((uint64_t)1 << 16) | ((uint64_t)(addr >> 4) & 0x3FFF);
}

#if HAS_TC
__device__ __forceinline__ void mma_bf16_ss(uint32_t d, uint64_t a, uint64_t b,
                                            uint32_t idesc, uint32_t en) {
    asm volatile(
        "{\n\t.reg .pred p;\n\tsetp.ne.u32 p, %4, 0;\n\t"
        "tcgen05.mma.cta_group::1.kind::f16 [%0], %1, %2, %3, {%5, %5, %5, %5}, p;\n\t}"
        :: "r"(d), "l"(a), "l"(b), "r"(idesc), "r"(en), "r"(0u) : "memory");
}
#define TC_ALLOC(sm, n)  asm volatile("tcgen05.alloc.cta_group::1.sync.aligned.shared::cta.b32 [%0], %1;" :: "r"(sm), "r"((uint32_t)(n)) : "memory")
#define TC_DEALLOC(t, n) asm volatile("tcgen05.dealloc.cta_group::1.sync.aligned.b32 %0, %1;" :: "r"(t), "r"((uint32_t)(n)))
#define TC_COMMIT(mb)    asm volatile("tcgen05.commit.cta_group::1.mbarrier::arrive::one.shared::cluster.b64 [%0];" :: "r"(mb) : "memory")
#define TC_FENCE_AFTER() asm volatile("tcgen05.fence::after_thread_sync;" ::: "memory")
#define TC_FENCE_BEFORE() asm volatile("tcgen05.fence::before_thread_sync;" ::: "memory")
#define TC_WAIT_LD()     asm volatile("tcgen05.wait::ld.sync.aligned;" ::: "memory")
#define LDTM32(r, a)                                                            \
    asm volatile("tcgen05.ld.sync.aligned.32x32b.x32.b32 "                      \
        "{%0,%1,%2,%3,%4,%5,%6,%7,%8,%9,%10,%11,%12,%13,%14,%15,"               \
        "%16,%17,%18,%19,%20,%21,%22,%23,%24,%25,%26,%27,%28,%29,%30,%31}, [%32];" \
        : "=r"((r)[0]),"=r"((r)[1]),"=r"((r)[2]),"=r"((r)[3]),                  \
          "=r"((r)[4]),"=r"((r)[5]),"=r"((r)[6]),"=r"((r)[7]),                  \
          "=r"((r)[8]),"=r"((r)[9]),"=r"((r)[10]),"=r"((r)[11]),                \
          "=r"((r)[12]),"=r"((r)[13]),"=r"((r)[14]),"=r"((r)[15]),              \
          "=r"((r)[16]),"=r"((r)[17]),"=r"((r)[18]),"=r"((r)[19]),              \
          "=r"((r)[20]),"=r"((r)[21]),"=r"((r)[22]),"=r"((r)[23]),              \
          "=r"((r)[24]),"=r"((r)[25]),"=r"((r)[26]),"=r"((r)[27]),              \
          "=r"((r)[28]),"=r"((r)[29]),"=r"((r)[30]),"=r"((r)[31])               \
        : "r"(a))
#define MB_WAIT(mb, par) do {                                                   \
    uint32_t _m = (mb), _p = (par), _d;                                         \
    asm volatile("{ .reg .pred p; mbarrier.try_wait.parity.acquire.cta.shared::cta.b64 p, [%1], %2; selp.b32 %0, 1, 0, p; }" \
                 : "=r"(_d) : "r"(_m), "r"(_p) : "memory");                     \
    if (!_d) {                                                                  \
        asm volatile("{ .reg .pred P1; W%=: mbarrier.try_wait.parity.acquire.cta.shared::cta.b64 P1, [%0], %1, 0x989680; @P1 bra.uni D%=; bra.uni W%=; D%=: }" \
                     :: "r"(_m), "r"(_p) : "memory");                           \
    }                                                                           \
} while (0)
#else
// compute_103 (non-'a') pass: stubs. Never executed (sm_103a cubin selected).
__device__ __forceinline__ void mma_bf16_ss(uint32_t, uint64_t, uint64_t, uint32_t, uint32_t) {}
#define TC_ALLOC(sm, n)   ((void)0)
#define TC_DEALLOC(t, n)  ((void)0)
#define TC_COMMIT(mb)     ((void)0)
#define TC_FENCE_AFTER()  ((void)0)
#define TC_FENCE_BEFORE() ((void)0)
#define TC_WAIT_LD()      ((void)0)
#define LDTM32(r, a)      do { _Pragma("unroll") for (int _i = 0; _i < 32; _i++) (r)[_i] = 0u; } while (0)
#define MB_WAIT(mb, par)  ((void)0)
#endif

#define MB_INIT(mb, c)   asm volatile("mbarrier.init.shared.b64 [%0], %1;" :: "r"(mb), "r"((uint32_t)(c)) : "memory")
#define MB_INVAL(mb)     asm volatile("mbarrier.inval.shared.b64 [%0];" :: "r"(mb) : "memory")
#define FENCE_ASYNC()    asm volatile("fence.proxy.async.shared::cta;" ::: "memory")
#define CP_ASYNC16(dst, src) asm volatile("cp.async.ca.shared.global [%0], [%1], 16;" :: "r"(dst), "l"(src) : "memory")
#define CP_COMMIT()      asm volatile("cp.async.commit_group;" ::: "memory")
#define CP_WAIT0()       asm volatile("cp.async.wait_group 0;" ::: "memory")

// ---------------- dtype detection (int32 vs int64 indices) ----------------
__global__ void detect_k(const unsigned int* __restrict__ e) {
    unsigned acc = 0;
    for (int i = 1; i < 128; i += 2) acc |= e[i];
    g_i64flag = (acc == 0u) ? 1 : 0;
}

// ---------------- weight split fp32 -> bf16 hi/lo ----------------
__global__ void wconv_k(const float* __restrict__ W1, const float* __restrict__ W2) {
    int i = blockIdx.x * 256 + threadIdx.x;
    const int tot = NLAYER * 256 * 128;
    if (i >= tot) return;
    int l = i / (256 * 128), rem = i % (256 * 128);
    {   // W1: [l][k(128)][n(256)] -> B1 [l][n][k]
        int n = rem / 128, k = rem % 128;
        float w = W1[l * 32768 + k * 256 + n];
        __nv_bfloat16 h = __float2bfloat16(w);
        g_b1hi[i] = h;
        g_b1lo[i] = __float2bfloat16(w - __bfloat162float(h));
    }
    {   // W2: [l][k(256)][n(128)] -> B2 [l][n][k]
        int n = rem / 256, k = rem % 256;
        float w = W2[l * 32768 + k * 128 + n];
        __nv_bfloat16 h = __float2bfloat16(w);
        g_b2hi[i] = h;
        g_b2lo[i] = __float2bfloat16(w - __bfloat162float(h));
    }
}

// ---------------- prep kernels ----------------
// prep0: hin = (1+eps0)*x ; zero all stats + pool accumulators
__global__ void prep0_k(const float4* __restrict__ x, const float* __restrict__ epsp, int n32) {
    int i = blockIdx.x * blockDim.x + threadIdx.x;
    if (i < n32) {
        float e = 1.0f + epsp[0];
        float4 v = x[i];
        ((float4*)g_hin)[i] = make_float4(v.x * e, v.y * e, v.z * e, v.w * e);
    }
    if (i < 256) { g_ssum[i] = 0.f; g_ssq[i] = 0.f; }
    if (i < 128) { g_ssum2[i] = 0.f; g_ssq2[i] = 0.f; }
    if (i < GCNT * 128) { g_ps[i] = 0.f; g_pmx[i] = 0.f; }
    if (i < GCNT) g_cnt[i] = 0.f;
}

// l>0: hin = (1+eps_l)*relu(bn(h2))   (x never materialized)
__global__ void prep_k(const float* __restrict__ epsp, int l, int n32) {
    int i = blockIdx.x * blockDim.x + threadIdx.x;
    if (i < n32) {
        float e = 1.0f + epsp[l];
        int c = (i & 31) * 4;
        float4 v = ((const float4*)g_h2)[i];
        float4 r;
        r.x = fmaxf(fmaf(v.x, g_scale[c + 0], g_shift[c + 0]), 0.f) * e;
        r.y = fmaxf(fmaf(v.y, g_scale[c + 1], g_shift[c + 1]), 0.f) * e;
        r.z = fmaxf(fmaf(v.z, g_scale[c + 2], g_shift[c + 2]), 0.f) * e;
        r.w = fmaxf(fmaf(v.w, g_scale[c + 3], g_shift[c + 3]), 0.f) * e;
        ((float4*)g_hin)[i] = r;
    }
}

// ---------------- edge scatter-add: hin[dst] += f(SRC[src]) ----------------
// 4 edges per warp (MLP=4). BN: apply relu(v*scale+shift) to gathered rows.
template<bool BN>
__global__ void scatter_k(const void* __restrict__ ei, const float* __restrict__ SRC,
                          long long E) {
    long long w = ((long long)blockIdx.x * blockDim.x + threadIdx.x) >> 5;
    int lane = threadIdx.x & 31;
    long long e0 = w * 4;
    if (e0 >= E) return;
    int cnt = (int)((E - e0 < 4) ? (E - e0) : 4);

    long long s[4], d[4];
    if (g_i64flag) {
        const long long* p = (const long long*)ei;
#pragma unroll
        for (int j = 0; j < 4; j++)
            if (j < cnt) { s[j] = p[e0 + j]; d[j] = p[E + e0 + j]; }
    } else {
        const int* p = (const int*)ei;
#pragma unroll
        for (int j = 0; j < 4; j++)
            if (j < cnt) { s[j] = (long long)p[e0 + j]; d[j] = (long long)p[E + e0 + j]; }
    }

    float4 v[4];
#pragma unroll
    for (int j = 0; j < 4; j++)
        if (j < cnt) v[j] = ((const float4*)SRC)[s[j] * 32 + lane];

    float sc0, sc1, sc2, sc3, sh0, sh1, sh2, sh3;
    if (BN) {
        int c = lane * 4;
        sc0 = g_scale[c]; sc1 = g_scale[c + 1]; sc2 = g_scale[c + 2]; sc3 = g_scale[c + 3];
        sh0 = g_shift[c]; sh1 = g_shift[c + 1]; sh2 = g_shift[c + 2]; sh3 = g_shift[c + 3];
    }

#pragma unroll
    for (int j = 0; j < 4; j++) {
        if (j < cnt) {
            float r0 = v[j].x, r1 = v[j].y, r2 = v[j].z, r3 = v[j].w;
            if (BN) {
                r0 = fmaxf(fmaf(r0, sc0, sh0), 0.f);
                r1 = fmaxf(fmaf(r1, sc1, sh1), 0.f);
                r2 = fmaxf(fmaf(r2, sc2, sh2), 0.f);
                r3 = fmaxf(fmaf(r3, sc3, sh3), 0.f);
            }
            float* dst = g_hin + d[j] * 128 + lane * 4;
            asm volatile("red.global.add.v4.f32 [%0], {%1, %2, %3, %4};"
                         :: "l"(dst), "f"(r0), "f"(r1), "f"(r2), "f"(r3) : "memory");
        }
    }
}

// ============ pipelined tcgen05 bf16x3 GEMM with fused BN-stats ============
// C[M,NC] = op(A)[M,K] @ W[K,NC] + bias.
// BNIN (GEMM2): per-CTA computes the y-BN scale/shift from raw g_ssum/g_ssq and
// applies relu(a*sc+sh) to A on staging. Stats of C go to g_ssum2 (BNIN) or g_ssum.
// Pipeline: A(next chunk) prefetched into regs + B(next) via cp.async double buffer
// while previous chunk's MMA runs.
#define SOFF_PTR  0
#define SOFF_MBAR 16
#define SOFF_SC   32                 // 256 floats
#define SOFF_SH   1056               // 256 floats
#define T_AHI 4096
#define T_ALO 20480
#define T_BHI0 36864
#define T_BLO0 53248
#define T_BHI1 69632
#define T_BLO1 86016
#define TG_SMEM 102400
// idesc kind::f16: dtype=F32(1<<4), atype=BF16(1<<7), btype=BF16(1<<10),
// N=128 (16<<17), M=128 (8<<24)
#define TG_IDESC 0x8200490u

__device__ __forceinline__ uint32_t pack_bf16x2(float a, float b) {
    __nv_bfloat162 h = __float22bfloat162_rn(make_float2(a, b));
    return *reinterpret_cast<uint32_t*>(&h);
}

template<bool BNIN>
__global__ void __launch_bounds__(256, 2) tgemm_k(
    const float* __restrict__ A,
    const __nv_bfloat16* __restrict__ Bhi, const __nv_bfloat16* __restrict__ Blo,
    const float* __restrict__ bias, float* __restrict__ C,
    const float* __restrict__ gamma, const float* __restrict__ beta, float invM,
    int M, int K, int NC)
{
    extern __shared__ char smem[];
    const uint32_t sb = smem_u32(smem);
    const int t = threadIdx.x, wid = t >> 5, lid = t & 31;
    const int bm = blockIdx.x * 128, bn = blockIdx.y * 128;
    float* sSc = reinterpret_cast<float*>(smem + SOFF_SC);
    float* sSh = reinterpret_cast<float*>(smem + SOFF_SH);

    if (wid == 0) TC_ALLOC(sb + SOFF_PTR, 128);
    if (t == 0) MB_INIT(sb + SOFF_MBAR, 1);
    if (BNIN) {   // t indexes all K=256 channels
        float m   = g_ssum[t] * invM;
        float var = g_ssq[t] * invM - m * m;
        float sc  = gamma[t] * rsqrtf(var + 1e-5f);
        sSc[t] = sc;
        sSh[t] = beta[t] - m * sc;
    }
    __syncthreads();
    uint32_t tmem;
    asm volatile("ld.shared.b32 %0, [%1];" : "=r"(tmem) : "r"(sb + SOFF_PTR));

    const uint64_t dAhi = make_desc(sb + T_AHI);
    const uint64_t dAlo = make_desc(sb + T_ALO);
    const uint64_t dBhi[2] = { make_desc(sb + T_BHI0), make_desc(sb + T_BHI1) };
    const uint64_t dBlo[2] = { make_desc(sb + T_BLO0), make_desc(sb + T_BLO1) };
    const int nch = K >> 6;

    // per-thread staging geometry (4 iterations of 256 threads cover 128x64)
    const int row = t >> 1;                 // wrong? no: see below
    (void)row;

    float4 apf[8];   // A prefetch: 4 its x 8 floats

#define PREF_A(CH)                                                              \
    {                                                                           \
        int kbase_ = (CH) * 64;                                                 \
        _Pragma("unroll")                                                       \
        for (int it = 0; it < 4; it++) {                                        \
            int idx = t + it * 256;                                             \
            int r_ = idx >> 3, kg_ = idx & 7;                                   \
            int grow_ = bm + r_;                                                \
            if (grow_ < M) {                                                    \
                const float* ap = A + (size_t)grow_ * K + kbase_ + kg_ * 8;     \
                apf[it * 2]     = *(const float4*)ap;                           \
                apf[it * 2 + 1] = *(const float4*)(ap + 4);                     \
            } else {                                                            \
                apf[it * 2]     = make_float4(0.f, 0.f, 0.f, 0.f);              \
                apf[it * 2 + 1] = make_float4(0.f, 0.f, 0.f, 0.f);              \
            }                                                                   \
        }                                                                       \
    }

#define CPASYNC_B(CH, BUF)                                                      \
    {                                                                           \
        int kbase_ = (CH) * 64;                                                 \
        uint32_t bhi_ = sb + ((BUF) ? T_BHI1 : T_BHI0);                         \
        uint32_t blo_ = sb + ((BUF) ? T_BLO1 : T_BLO0);                         \
        _Pragma("unroll")                                                       \
        for (int it = 0; it < 4; it++) {                                        \
            int idx = t + it * 256;                                             \
            int r_ = idx >> 3, kg_ = idx & 7;                                   \
            uint32_t so_ = SW128((uint32_t)(r_ * 128 + kg_ * 16));              \
            size_t bo_ = (size_t)(bn + r_) * K + kbase_ + kg_ * 8;              \
            CP_ASYNC16(bhi_ + so_, Bhi + bo_);                                  \
            CP_ASYNC16(blo_ + so_, Blo + bo_);                                  \
        }                                                                       \
        CP_COMMIT();                                                            \
    }

#define STORE_A(CH)                                                             \
    {                                                                           \
        int kbase_ = (CH) * 64;                                                 \
        _Pragma("unroll")                                                       \
        for (int it = 0; it < 4; it++) {                                        \
            int idx = t + it * 256;                                             \
            int r_ = idx >> 3, kg_ = idx & 7;                                   \
            uint32_t so_ = SW128((uint32_t)(r_ * 128 + kg_ * 16));              \
            float f[8];                                                         \
            *(float4*)(f)     = apf[it * 2];                                    \
            *(float4*)(f + 4) = apf[it * 2 + 1];                                \
            if (BNIN) {                                                         \
                int cb_ = kbase_ + kg_ * 8;                                     \
                _Pragma("unroll")                                               \
                for (int j = 0; j < 8; j++)                                     \
                    f[j] = fmaxf(fmaf(f[j], sSc[cb_ + j], sSh[cb_ + j]), 0.f);  \
            }                                                                   \
            uint32_t h[4], lo[4];                                               \
            _Pragma("unroll")                                                   \
            for (int j = 0; j < 4; j++) {                                       \
                h[j] = pack_bf16x2(f[2 * j], f[2 * j + 1]);                     \
                __nv_bfloat162 hb = *reinterpret_cast<__nv_bfloat162*>(&h[j]);  \
                float2 hr = __bfloat1622float2(hb);                             \
                lo[j] = pack_bf16x2(f[2 * j] - hr.x, f[2 * j + 1] - hr.y);      \
            }                                                                   \
            *(uint4*)(smem + T_AHI + so_) = make_uint4(h[0], h[1], h[2], h[3]); \
            *(uint4*)(smem + T_ALO + so_) = make_uint4(lo[0], lo[1], lo[2], lo[3]); \
        }                                                                       \
    }

    // ---- prologue: chunk 0 ----
    PREF_A(0);
    CPASYNC_B(0, 0);
    STORE_A(0);
    CP_WAIT0();
    FENCE_ASYNC();
    __syncthreads();
    if (wid == 0 && elect_one()) {
#pragma unroll
        for (int s = 0; s < 4; s++)
            mma_bf16_ss(tmem, dAhi + s * 2, dBhi[0] + s * 2, TG_IDESC, s == 0 ? 0u : 1u);
#pragma unroll
        for (int s = 0; s < 4; s++)
            mma_bf16_ss(tmem, dAhi + s * 2, dBlo[0] + s * 2, TG_IDESC, 1u);
#pragma unroll
        for (int s = 0; s < 4; s++)
            mma_bf16_ss(tmem, dAlo + s * 2, dBhi[0] + s * 2, TG_IDESC, 1u);
        TC_COMMIT(sb + SOFF_MBAR);
    }

    // ---- pipelined chunks ----
    for (int ch = 1; ch < nch; ch++) {
        int buf = ch & 1;
        PREF_A(ch);
        CPASYNC_B(ch, buf);
        MB_WAIT(sb + SOFF_MBAR, (ch - 1) & 1);   // MMA(ch-1) done: A smem free
        STORE_A(ch);
        CP_WAIT0();
        FENCE_ASYNC();
        __syncthreads();
        if (wid == 0 && elect_one()) {
#pragma unroll
            for (int s = 0; s < 4; s++)
                mma_bf16_ss(tmem, dAhi + s * 2, dBhi[buf] + s * 2, TG_IDESC, 1u);
#pragma unroll
            for (int s = 0; s < 4; s++)
                mma_bf16_ss(tmem, dAhi + s * 2, dBlo[buf] + s * 2, TG_IDESC, 1u);
#pragma unroll
            for (int s = 0; s < 4; s++)
                mma_bf16_ss(tmem, dAlo + s * 2, dBhi[buf] + s * 2, TG_IDESC, 1u);
            TC_COMMIT(sb + SOFF_MBAR);
        }
    }
    MB_WAIT(sb + SOFF_MBAR, (nch - 1) & 1);
    TC_FENCE_AFTER();

#undef PREF_A
#undef CPASYNC_B
#undef STORE_A

    // ---- epilogue: bias, store C, stash rows in smem for stats ----
    float* buf = reinterpret_cast<float*>(smem + T_AHI);   // [128][129]
    if (wid < 4) {
        int r = wid * 32 + lid;
        int grow = bm + r;
#pragma unroll
        for (int b = 0; b < 4; b++) {
            uint32_t rg[32];
            LDTM32(rg, tmem + b * 32);
            TC_WAIT_LD();
            float v[32];
#pragma unroll
            for (int i = 0; i < 32; i++)
                v[i] = __uint_as_float(rg[i]) + bias[bn + b * 32 + i];
            if (grow < M) {
#pragma unroll
                for (int q = 0; q < 8; q++)
                    *(float4*)(C + (size_t)grow * NC + bn + b * 32 + q * 4) = *(float4*)(v + q * 4);
            }
#pragma unroll
            for (int i = 0; i < 32; i++)
                buf[r * 129 + b * 32 + i] = v[i];
        }
        TC_FENCE_BEFORE();
    }
    __syncthreads();

    // ---- column stats ----
    {
        float* ssum_t = BNIN ? g_ssum2 : g_ssum;
        float* ssq_t  = BNIN ? g_ssq2  : g_ssq;
        int c = t & 127, h = t >> 7;
        float s = 0.f, q = 0.f;
#pragma unroll 8
        for (int rr = 0; rr < 64; rr++) {
            int r = h * 64 + rr;
            if (bm + r < M) {
                float v = buf[r * 129 + c];
                s += v;
                q = fmaf(v, v, q);
            }
        }
        atomicAdd(&ssum_t[bn + c], s);
        atomicAdd(&ssq_t[bn + c], q);
    }
    __syncthreads();
    if (t == 0) MB_INVAL(sb + SOFF_MBAR);
    if (wid == 0) TC_DEALLOC(tmem, 128);
}

// outer BN finalize: scale/shift for h2; zero both stats sets for next layer
__global__ void finalize_k(const float* __restrict__ gamma, const float* __restrict__ beta,
                           float invM) {
    int t = threadIdx.x;  // 256
    if (t < 128) {
        float m   = g_ssum2[t] * invM;
        float var = g_ssq2[t] * invM - m * m;
        float sc  = gamma[t] * rsqrtf(var + 1e-5f);
        g_scale[t] = sc;
        g_shift[t] = beta[t] - m * sc;
        g_ssum2[t] = 0.f;
        g_ssq2[t]  = 0.f;
    }
    g_ssum[t] = 0.f;
    g_ssq[t]  = 0.f;
}

// ---------------- readout pooling ----------------
__global__ void pool_k(const void* __restrict__ batch, int n) {
    long long t = (long long)blockIdx.x * blockDim.x + threadIdx.x;
    long long i = t >> 5;
    if (i >= n) return;
    int lane = (int)(t & 31);
    long long g;
    if (g_i64flag) g = ((const long long*)batch)[i];
    else           g = (long long)((const int*)batch)[i];
    int c = lane * 4;
    float4 v = ((const float4*)g_h2)[i * 32 + lane];
    float r0 = fmaxf(fmaf(v.x, g_scale[c + 0], g_shift[c + 0]), 0.f);
    float r1 = fmaxf(fmaf(v.y, g_scale[c + 1], g_shift[c + 1]), 0.f);
    float r2 = fmaxf(fmaf(v.z, g_scale[c + 2], g_shift[c + 2]), 0.f);
    float r3 = fmaxf(fmaf(v.w, g_scale[c + 3], g_shift[c + 3]), 0.f);
    float* ps = g_ps + g * 128 + c;
    asm volatile("red.global.add.v4.f32 [%0], {%1, %2, %3, %4};"
                 :: "l"(ps), "f"(r0), "f"(r1), "f"(r2), "f"(r3) : "memory");
    unsigned int* mx = (unsigned int*)(g_pmx + g * 128 + c);
    atomicMax(mx + 0, __float_as_uint(r0));
    atomicMax(mx + 1, __float_as_uint(r1));
    atomicMax(mx + 2, __float_as_uint(r2));
    atomicMax(mx + 3, __float_as_uint(r3));
    if (lane == 0) atomicAdd(&g_cnt[g], 1.0f);
}

// ---------------- classifier ----------------
__global__ void cgemm1_k(const float* __restrict__ cW1, const float* __restrict__ cb1) {
    int g = blockIdx.x;
    int j = threadIdx.x;  // 128
    __shared__ float z[384];
    float cnt = fmaxf(g_cnt[g], 1.0f);
    float sv = g_ps[g * 128 + j];
    z[j]       = sv;
    z[128 + j] = sv / cnt;
    z[256 + j] = g_pmx[g * 128 + j];
    __syncthreads();
    float acc = cb1[j];
#pragma unroll 8
    for (int k = 0; k < 384; k++)
        acc = fmaf(z[k], cW1[k * 128 + j], acc);
    g_z1[g * 128 + j] = acc;
}

__global__ void cstats_k(const float* __restrict__ cg, const float* __restrict__ cbeta) {
    int j = threadIdx.x;  // 128
    float s = 0.f, q = 0.f;
    for (int g = 0; g < GCNT; g++) {
        float v = g_z1[g * 128 + j];
        s += v; q += v * v;
    }
    float m   = s * (1.0f / GCNT);
    float var = q * (1.0f / GCNT) - m * m;
    float sc  = cg[j] * rsqrtf(var + 1e-5f);
    g_scale[j] = sc;
    g_shift[j] = cbeta[j] - m * sc;
}

__global__ void chead_k(const float* __restrict__ cW2, const float* __restrict__ cb2,
                        const float* __restrict__ cW3, const float* __restrict__ cb3,
                        float* __restrict__ out) {
    int g = blockIdx.x;
    int j = threadIdx.x;  // 64
    __shared__ float a[128];
    __shared__ float z2[64];
    for (int k = j; k < 128; k += 64)
        a[k] = fmaxf(fmaf(g_z1[g * 128 + k], g_scale[k], g_shift[k]), 0.f);
    __syncthreads();
    float acc = cb2[j];
#pragma unroll 8
    for (int k = 0; k < 128; k++)
        acc = fmaf(a[k], cW2[k * 64 + j], acc);
    z2[j] = fmaxf(acc, 0.f);
    __syncthreads();
    if (j < 2) {
        float o = cb3[j];
#pragma unroll 8
        for (int k = 0; k < 64; k++)
            o = fmaf(z2[k], cW3[k * 2 + j], o);
        out[g * 2 + j] = o;
    }
}

// ---------------- launcher ----------------
extern "C" void kernel_launch(void* const* d_in, const int* in_sizes, int n_in,
                              void* d_out, int out_size) {
    const float* x     = (const float*)d_in[0];
    const void*  ei    = d_in[1];
    const void*  batch = d_in[2];
    int base = (in_sizes[3] == 1) ? 4 : 3;
    const float* W1    = (const float*)d_in[base + 0];
    const float* b1    = (const float*)d_in[base + 1];
    const float* g1    = (const float*)d_in[base + 2];
    const float* be1   = (const float*)d_in[base + 3];
    const float* W2    = (const float*)d_in[base + 4];
    const float* b2    = (const float*)d_in[base + 5];
    const float* gbn   = (const float*)d_in[base + 6];
    const float* bbn   = (const float*)d_in[base + 7];
    const float* eps   = (const float*)d_in[base + 8];
    const float* cW1   = (const float*)d_in[base + 9];
    const float* cb1   = (const float*)d_in[base + 10];
    const float* cg    = (const float*)d_in[base + 11];
    const float* cbeta = (const float*)d_in[base + 12];
    const float* cW2   = (const float*)d_in[base + 13];
    const float* cb2   = (const float*)d_in[base + 14];
    const float* cW3   = (const float*)d_in[base + 15];
    const float* cb3   = (const float*)d_in[base + 16];

    int n = in_sizes[0] / 128;
    long long E = (long long)in_sizes[1] / 2;
    int n32 = n * 32;
    int nb = (n32 + 255) / 256;
    int gx = (n + 127) / 128;
    long long nwarp = (E + 3) / 4;
    int sblk = (int)((nwarp * 32 + 255) / 256);
    float invM = 1.0f / (float)n;

    static int smem_set = 0;
    if (!smem_set) {
        cudaFuncSetAttribute(tgemm_k<false>, cudaFuncAttributeMaxDynamicSharedMemorySize, TG_SMEM);
        cudaFuncSetAttribute(tgemm_k<true>,  cudaFuncAttributeMaxDynamicSharedMemorySize, TG_SMEM);
        smem_set = 1;
    }

    float *p_hin, *p_y, *p_h2;
    __nv_bfloat16 *p_b1hi, *p_b1lo, *p_b2hi, *p_b2lo;
    cudaGetSymbolAddress((void**)&p_hin, g_hin);
    cudaGetSymbolAddress((void**)&p_y,   g_y);
    cudaGetSymbolAddress((void**)&p_h2,  g_h2);
    cudaGetSymbolAddress((void**)&p_b1hi, g_b1hi);
    cudaGetSymbolAddress((void**)&p_b1lo, g_b1lo);
    cudaGetSymbolAddress((void**)&p_b2hi, g_b2hi);
    cudaGetSymbolAddress((void**)&p_b2lo, g_b2lo);

    detect_k<<<1, 1>>>((const unsigned int*)ei);
    wconv_k<<<(NLAYER * 256 * 128 + 255) / 256, 256>>>(W1, W2);
    prep0_k<<<nb, 256>>>((const float4*)x, eps, n32);

    for (int l = 0; l < 4; l++) {
        if (l > 0) {
            prep_k<<<nb, 256>>>(eps, l, n32);
            scatter_k<true><<<sblk, 256>>>(ei, p_h2, E);
        } else {
            scatter_k<false><<<sblk, 256>>>(ei, x, E);
        }
        tgemm_k<false><<<dim3(gx, 2), 256, TG_SMEM>>>(
            p_hin, p_b1hi + (size_t)l * 32768, p_b1lo + (size_t)l * 32768,
            b1 + l * 256, p_y, nullptr, nullptr, invM, n, 128, 256);
        tgemm_k<true><<<dim3(gx, 1), 256, TG_SMEM>>>(
            p_y, p_b2hi + (size_t)l * 32768, p_b2lo + (size_t)l * 32768,
            b2 + l * 128, p_h2, g1 + l * 256, be1 + l * 256, invM, n, 256, 128);
        finalize_k<<<1, 256>>>(gbn + l * 128, bbn + l * 128, invM);
    }

    pool_k<<<nb, 256>>>(batch, n);
    cgemm1_k<<<GCNT, 128>>>(cW1, cb1);
    cstats_k<<<1, 128>>>(cg, cbeta);
    chead_k<<<GCNT, 64>>>(cW2, cb2, cW3, cb3, (float*)d_out);
}